// round 1
// baseline (speedup 1.0000x reference)
#include <cuda_runtime.h>
#include <math.h>

#define B_ 128
#define T_ 64
#define E_ 2048
#define H_ 1024
#define R_ 8
#define H3 3072

// ---------------- scratch (static device, allocation-free) ----------------
__device__ float d_GI_s[(size_t)B_ * T_ * H3];   // enc @ ws_ih[:, :E]^T
__device__ float d_GI_a[(size_t)B_ * T_ * H3];   // enc @ wa_ih[:, :E]^T
__device__ float d_GI_o[(size_t)B_ * T_ * H3];   // enc @ wo_ih^T
__device__ float d_G[1280 * H3];                 // per-step gate GEMM results
// transposed weights, layout [K][3072] (n contiguous)
__device__ float d_WT_hh_s[H_ * H3];
__device__ float d_WT_hh_a[H_ * H3];
__device__ float d_WT_hh_o[H_ * H3];
__device__ float d_WT_ihE_s[E_ * H3];
__device__ float d_WT_ihE_a[E_ * H3];
__device__ float d_WT_ihE_o[E_ * H3];
__device__ float d_WT_ihH_s[H_ * H3];
__device__ float d_WT_ihH_a[H_ * H3];

// ---------------- packed f32x2 helpers ----------------
__device__ __forceinline__ unsigned long long pk2(float lo, float hi) {
    unsigned long long r;
    asm("mov.b64 %0, {%1, %2};" : "=l"(r)
        : "r"(__float_as_uint(lo)), "r"(__float_as_uint(hi)));
    return r;
}
__device__ __forceinline__ void unpk2(unsigned long long v, float& lo, float& hi) {
    unsigned int a, b;
    asm("mov.b64 {%0, %1}, %2;" : "=r"(a), "=r"(b) : "l"(v));
    lo = __uint_as_float(a);
    hi = __uint_as_float(b);
}
__device__ __forceinline__ void fma2(unsigned long long& acc,
                                     unsigned long long a, unsigned long long b) {
    asm("fma.rn.f32x2 %0, %1, %2, %0;" : "+l"(acc) : "l"(a), "l"(b));
}

// ---------------- weight transpose: dst[c][r] = src[r][col_off + c] ----------------
// src has 3072 rows, row stride ld. dst row stride 3072.
__global__ void transpose_k(const float* __restrict__ src, int ld, int col_off,
                            float* __restrict__ dst) {
    __shared__ float tile[32][33];
    int c0 = blockIdx.x * 32, r0 = blockIdx.y * 32;
    int tx = threadIdx.x, ty = threadIdx.y;  // 32 x 8
#pragma unroll
    for (int i = ty; i < 32; i += 8)
        tile[i][tx] = src[(size_t)(r0 + i) * ld + col_off + c0 + tx];
    __syncthreads();
#pragma unroll
    for (int i = ty; i < 32; i += 8)
        dst[(size_t)(c0 + i) * H3 + r0 + tx] = tile[tx][i];
}

// ---------------- 128x128 fp32 GEMM tile, f32x2 micro-kernel ----------------
// C(128x128) += Arows(128 x KDIM, gathered via rowmap) * WT(KDIM x 3072, pre-offset to n0)
template <int KDIM>
__device__ __forceinline__ void gemm_tile(const float* __restrict__ Abase, int astride,
                                          const int* __restrict__ rowmap,
                                          const float* __restrict__ WTn,
                                          float* __restrict__ Cmn) {
    __shared__ float As[16][132];
    __shared__ float Bs[16][132];
    const int tid = threadIdx.x;
    const int tx = tid & 15, ty = tid >> 4;

    unsigned long long acc[8][4];
#pragma unroll
    for (int i = 0; i < 8; i++)
#pragma unroll
        for (int j = 0; j < 4; j++) acc[i][j] = 0ULL;

    for (int k0 = 0; k0 < KDIM; k0 += 16) {
#pragma unroll
        for (int i = 0; i < 2; i++) {
            int idx = tid + (i << 8);
            int row = idx >> 2;
            int kg = (idx & 3) << 2;
            const float4 v =
                *(const float4*)(Abase + (size_t)rowmap[row] * astride + k0 + kg);
            As[kg + 0][row] = v.x;
            As[kg + 1][row] = v.y;
            As[kg + 2][row] = v.z;
            As[kg + 3][row] = v.w;
        }
#pragma unroll
        for (int i = 0; i < 2; i++) {
            int idx = tid + (i << 8);
            int kk = idx >> 5;
            int n4 = (idx & 31) << 2;
            *(float4*)&Bs[kk][n4] =
                *(const float4*)(WTn + (size_t)(k0 + kk) * H3 + n4);
        }
        __syncthreads();
#pragma unroll
        for (int kk = 0; kk < 16; kk++) {
            float4 a0 = *(const float4*)&As[kk][ty << 3];
            float4 a1 = *(const float4*)&As[kk][(ty << 3) + 4];
            float4 b0 = *(const float4*)&Bs[kk][tx << 3];
            float4 b1 = *(const float4*)&Bs[kk][(tx << 3) + 4];
            unsigned long long bp[4] = {pk2(b0.x, b0.y), pk2(b0.z, b0.w),
                                        pk2(b1.x, b1.y), pk2(b1.z, b1.w)};
            float av[8] = {a0.x, a0.y, a0.z, a0.w, a1.x, a1.y, a1.z, a1.w};
#pragma unroll
            for (int i = 0; i < 8; i++) {
                unsigned long long ad = pk2(av[i], av[i]);
#pragma unroll
                for (int j = 0; j < 4; j++) fma2(acc[i][j], ad, bp[j]);
            }
        }
        __syncthreads();
    }
#pragma unroll
    for (int i = 0; i < 8; i++) {
        float o[8];
#pragma unroll
        for (int j = 0; j < 4; j++) unpk2(acc[i][j], o[2 * j], o[2 * j + 1]);
        float* cp = Cmn + (size_t)((ty << 3) + i) * H3 + (tx << 3);
        *(float4*)cp = make_float4(o[0], o[1], o[2], o[3]);
        *(float4*)(cp + 4) = make_float4(o[4], o[5], o[6], o[7]);
    }
}

// ---------------- precompute: GI_x = enc @ WT_ihE_x ----------------
__global__ __launch_bounds__(256, 2) void pre_gemm(const float* __restrict__ enc) {
    __shared__ int rowmap[128];
    int m0 = blockIdx.y << 7;
    if (threadIdx.x < 128) rowmap[threadIdx.x] = m0 + threadIdx.x;
    __syncthreads();
    const float* WT;
    float* C;
    if (blockIdx.z == 0) { WT = d_WT_ihE_s; C = d_GI_s; }
    else if (blockIdx.z == 1) { WT = d_WT_ihE_a; C = d_GI_a; }
    else { WT = d_WT_ihE_o; C = d_GI_o; }
    int n0 = blockIdx.x << 7;
    gemm_tile<E_>(enc, E_, rowmap, WT + n0, C + (size_t)m0 * H3 + n0);
}

// ---------------- per-step gathered GEMMs ----------------
// virtual row layout in d_G (1280 rows x 3072):
//   [0,128)     spk gh:    A[b,spk] @ ws_hh^T
//   [128,256)   adr gh:    A[b,adr] @ wa_hh^T
//   [256,1024)  oth gh:    A[b,oth_k] @ wo_hh^T   (k ascending non-spk/adr)
//   [1024,1152) spk ih-st: A[b,adr] @ ws_ih[:,E:]^T
//   [1152,1280) adr ih-st: A[b,spk] @ wa_ih[:,E:]^T
__global__ __launch_bounds__(256, 2) void step_gemm(const float* __restrict__ A,
                                                    const int* __restrict__ dig, int t) {
    __shared__ int rowmap[128];
    int my = blockIdx.y;
    int m0 = my << 7;
    if (threadIdx.x < 128) {
        int i = threadIdx.x;
        int m = m0 + i;
        int b, role;
        if (m < 256 || m >= 1024) {
            b = i;
            int which = (my == 0) ? 0 : (my == 1) ? 1 : (my == 8) ? 1 : 0;
            role = dig[((size_t)(b * T_ + t)) * 2 + which];
        } else {
            int idx = m - 256;
            b = idx / 6;
            int k = idx % 6;
            int spk = dig[((size_t)(b * T_ + t)) * 2];
            int adr = dig[((size_t)(b * T_ + t)) * 2 + 1];
            int cnt = 0;
            role = 0;
#pragma unroll
            for (int rr = 0; rr < R_; rr++) {
                if (rr != spk && rr != adr) {
                    if (cnt == k) role = rr;
                    cnt++;
                }
            }
        }
        rowmap[i] = (b << 3) + role;
    }
    __syncthreads();
    const float* WT = (my == 0) ? d_WT_hh_s
                    : (my == 1) ? d_WT_hh_a
                    : (my < 8)  ? d_WT_hh_o
                    : (my == 8) ? d_WT_ihH_s
                                : d_WT_ihH_a;
    int n0 = blockIdx.x << 7;
    gemm_tile<H_>(A, H_, rowmap, WT + n0, d_G + (size_t)m0 * H3 + n0);
}

// ---------------- pointwise GRU update (in place on A) ----------------
__global__ __launch_bounds__(256) void gru_pointwise(
    float* __restrict__ A, const int* __restrict__ dig, int t,
    const float* __restrict__ bih_s, const float* __restrict__ bhh_s,
    const float* __restrict__ bih_a, const float* __restrict__ bhh_a,
    const float* __restrict__ bih_o, const float* __restrict__ bhh_o) {
    int idx = blockIdx.x * 256 + threadIdx.x;  // < B*R*H
    int h = idx & (H_ - 1);
    int br = idx >> 10;
    int r = br & 7, b = br >> 3;
    int spk = dig[((size_t)(b * T_ + t)) * 2];
    int adr = dig[((size_t)(b * T_ + t)) * 2 + 1];
    const float *GI, *gihs = nullptr, *bih, *bhh;
    int ghrow;
    if (r == spk) {
        ghrow = b; gihs = d_G + (size_t)(1024 + b) * H3;
        GI = d_GI_s; bih = bih_s; bhh = bhh_s;
    } else if (r == adr) {
        ghrow = 128 + b; gihs = d_G + (size_t)(1152 + b) * H3;
        GI = d_GI_a; bih = bih_a; bhh = bhh_a;
    } else {
        int k = r - (spk < r ? 1 : 0) - (adr < r ? 1 : 0);
        ghrow = 256 + b * 6 + k;
        GI = d_GI_o; bih = bih_o; bhh = bhh_o;
    }
    const float* gi = GI + (size_t)(b * T_ + t) * H3;
    const float* gh = d_G + (size_t)ghrow * H3;
    float gir = gi[h] + bih[h];
    float giz = gi[H_ + h] + bih[H_ + h];
    float gin = gi[2 * H_ + h] + bih[2 * H_ + h];
    if (gihs) {
        gir += gihs[h];
        giz += gihs[H_ + h];
        gin += gihs[2 * H_ + h];
    }
    float ghr = gh[h] + bhh[h];
    float ghz = gh[H_ + h] + bhh[H_ + h];
    float ghn = gh[2 * H_ + h] + bhh[2 * H_ + h];
    float rg = 1.f / (1.f + expf(-(gir + ghr)));
    float zg = 1.f / (1.f + expf(-(giz + ghz)));
    float ng = tanhf(gin + rg * ghn);
    float hold = A[idx];
    A[idx] = (1.f - zg) * ng + zg * hold;
}

static float* sym_addr(const void* sym) {
    void* p = nullptr;
    cudaGetSymbolAddress(&p, sym);
    return (float*)p;
}

extern "C" void kernel_launch(void* const* d_in, const int* in_sizes, int n_in,
                              void* d_out, int out_size) {
    (void)in_sizes; (void)n_in; (void)out_size;
    const float* enc    = (const float*)d_in[0];
    const int*   dig    = (const int*)d_in[1];
    const float* ws_ih  = (const float*)d_in[2];
    const float* ws_hh  = (const float*)d_in[3];
    const float* ws_bih = (const float*)d_in[4];
    const float* ws_bhh = (const float*)d_in[5];
    const float* wa_ih  = (const float*)d_in[6];
    const float* wa_hh  = (const float*)d_in[7];
    const float* wa_bih = (const float*)d_in[8];
    const float* wa_bhh = (const float*)d_in[9];
    const float* wo_ih  = (const float*)d_in[10];
    const float* wo_hh  = (const float*)d_in[11];
    const float* wo_bih = (const float*)d_in[12];
    const float* wo_bhh = (const float*)d_in[13];
    float* A = (float*)d_out;

    // A0 = zeros
    cudaMemsetAsync(d_out, 0, (size_t)B_ * R_ * H_ * sizeof(float), 0);

    float* WT_hh_s  = sym_addr(d_WT_hh_s);
    float* WT_hh_a  = sym_addr(d_WT_hh_a);
    float* WT_hh_o  = sym_addr(d_WT_hh_o);
    float* WT_ihE_s = sym_addr(d_WT_ihE_s);
    float* WT_ihE_a = sym_addr(d_WT_ihE_a);
    float* WT_ihE_o = sym_addr(d_WT_ihE_o);
    float* WT_ihH_s = sym_addr(d_WT_ihH_s);
    float* WT_ihH_a = sym_addr(d_WT_ihH_a);

    dim3 tb(32, 8);
    transpose_k<<<dim3(1024 / 32, 96), tb>>>(ws_hh, 1024, 0, WT_hh_s);
    transpose_k<<<dim3(1024 / 32, 96), tb>>>(wa_hh, 1024, 0, WT_hh_a);
    transpose_k<<<dim3(1024 / 32, 96), tb>>>(wo_hh, 1024, 0, WT_hh_o);
    transpose_k<<<dim3(2048 / 32, 96), tb>>>(ws_ih, 3072, 0, WT_ihE_s);
    transpose_k<<<dim3(2048 / 32, 96), tb>>>(wa_ih, 3072, 0, WT_ihE_a);
    transpose_k<<<dim3(2048 / 32, 96), tb>>>(wo_ih, 2048, 0, WT_ihE_o);
    transpose_k<<<dim3(1024 / 32, 96), tb>>>(ws_ih, 3072, 2048, WT_ihH_s);
    transpose_k<<<dim3(1024 / 32, 96), tb>>>(wa_ih, 3072, 2048, WT_ihH_a);

    // state-independent gi precompute for all (b, t)
    pre_gemm<<<dim3(24, 64, 3), 256>>>(enc);

    // sequential scan
    for (int t = 0; t < T_; t++) {
        step_gemm<<<dim3(24, 10), 256>>>(A, dig, t);
        gru_pointwise<<<4096, 256>>>(A, dig, t, ws_bih, ws_bhh, wa_bih, wa_bhh,
                                     wo_bih, wo_bhh);
    }
}

// round 3
// speedup vs baseline: 2.9516x; 2.9516x over previous
#include <cuda_runtime.h>
#include <cuda_bf16.h>
#include <cstdint>
#include <math.h>

#define B_ 128
#define T_ 64
#define E_ 2048
#define H_ 1024
#define R_ 8
#define H3 3072

// ==================== helpers (baseline PTX only, no 'a' features) ====================
__device__ __forceinline__ uint32_t smem_to_u32(const void* p) {
    uint32_t a;
    asm("{ .reg .u64 t; cvta.to.shared.u64 t, %1; cvt.u32.u64 %0, t; }"
        : "=r"(a) : "l"(p));
    return a;
}
__device__ __forceinline__ uint32_t swz(uint32_t b) { return b ^ ((b >> 3) & 0x70); }

__device__ __forceinline__ void cpa16(uint32_t dst, const void* src) {
    asm volatile("cp.async.cg.shared.global [%0], [%1], 16;" :: "r"(dst), "l"(src));
}
__device__ __forceinline__ void ldm_x4(uint32_t* r, uint32_t a) {
    asm volatile("ldmatrix.sync.aligned.m8n8.x4.shared.b16 {%0,%1,%2,%3}, [%4];"
                 : "=r"(r[0]), "=r"(r[1]), "=r"(r[2]), "=r"(r[3]) : "r"(a));
}
__device__ __forceinline__ void mma16816(float* c, const uint32_t* a, const uint32_t* b) {
    asm volatile(
        "mma.sync.aligned.m16n8k16.row.col.f32.bf16.bf16.f32 "
        "{%0,%1,%2,%3}, {%4,%5,%6,%7}, {%8,%9}, {%0,%1,%2,%3};"
        : "+f"(c[0]), "+f"(c[1]), "+f"(c[2]), "+f"(c[3])
        : "r"(a[0]), "r"(a[1]), "r"(a[2]), "r"(a[3]), "r"(b[0]), "r"(b[1]));
}

// ==================== scratch (static device, allocation-free) ====================
__device__ float d_GI_s[(size_t)B_ * T_ * H3];
__device__ float d_GI_a[(size_t)B_ * T_ * H3];
__device__ float d_GI_o[(size_t)B_ * T_ * H3];
__device__ float d_G[1280 * H3];

__device__ __nv_bfloat16 d_enc_hi[(size_t)B_ * T_ * E_];
__device__ __nv_bfloat16 d_enc_lo[(size_t)B_ * T_ * E_];
__device__ __nv_bfloat16 d_S_hi[(size_t)B_ * R_ * H_];
__device__ __nv_bfloat16 d_S_lo[(size_t)B_ * R_ * H_];

// weight images: pre-swizzled SMEM-tile layout.
// element (n,k) of W[3072][Kw] -> nt=n>>8, r=n&255, kc=k>>6, j=k&63
//   elem_off = (nt*(Kw/64)+kc)*16384 + SWZ(r*128 + j*2)/2
__device__ __nv_bfloat16 d_whh_s_hi[3072 * 1024], d_whh_s_lo[3072 * 1024];
__device__ __nv_bfloat16 d_whh_a_hi[3072 * 1024], d_whh_a_lo[3072 * 1024];
__device__ __nv_bfloat16 d_whh_o_hi[3072 * 1024], d_whh_o_lo[3072 * 1024];
__device__ __nv_bfloat16 d_wihE_s_hi[3072 * 2048], d_wihE_s_lo[3072 * 2048];
__device__ __nv_bfloat16 d_wihE_a_hi[3072 * 2048], d_wihE_a_lo[3072 * 2048];
__device__ __nv_bfloat16 d_wihE_o_hi[3072 * 2048], d_wihE_o_lo[3072 * 2048];
__device__ __nv_bfloat16 d_wihH_s_hi[3072 * 1024], d_wihH_s_lo[3072 * 1024];
__device__ __nv_bfloat16 d_wihH_a_hi[3072 * 1024], d_wihH_a_lo[3072 * 1024];

// ==================== conversion kernels ====================
__global__ void conv_enc(const float* __restrict__ enc) {
    size_t idx = (size_t)blockIdx.x * 256 + threadIdx.x;
    float x = enc[idx];
    __nv_bfloat16 h = __float2bfloat16(x);
    d_enc_hi[idx] = h;
    d_enc_lo[idx] = __float2bfloat16(x - __bfloat162float(h));
}

__global__ void conv_w(const float* __restrict__ src, int ld, int col_off, int kbits,
                       __nv_bfloat16* __restrict__ hi, __nv_bfloat16* __restrict__ lo) {
    size_t idx = (size_t)blockIdx.x * 256 + threadIdx.x;
    int kw = 1 << kbits;
    int n = (int)(idx >> kbits);
    int k = (int)(idx & (kw - 1));
    float x = src[(size_t)n * ld + col_off + k];
    __nv_bfloat16 h = __float2bfloat16(x);
    __nv_bfloat16 l = __float2bfloat16(x - __bfloat162float(h));
    int nt = n >> 8, r = n & 255, kc = k >> 6, j = k & 63;
    size_t base = ((size_t)(nt * (kw >> 6) + kc)) << 14;
    uint32_t byte = (uint32_t)((r << 7) + (j << 1));
    size_t off = base + (swz(byte) >> 1);
    hi[off] = h;
    lo[off] = l;
}

// ==================== mma.sync GEMM core ====================
// SMEM per stage: {A_hi 16K, A_lo 16K, W_hi 32K, W_lo 32K} = 96K, x2 stages
static constexpr int OFF_STAGE = 1024;
static constexpr int SA_HI = 0;
static constexpr int SA_LO = 16384;
static constexpr int SW_HI = 32768;
static constexpr int SW_LO = 65536;
static constexpr int STAGE_BYTES = 98304;
static constexpr int SMEM_TOTAL = OFF_STAGE + 2 * STAGE_BYTES;  // 197632

__device__ __forceinline__ void load_a_tile(uint32_t dst, const __nv_bfloat16* __restrict__ base,
                                            int astride, const int* __restrict__ rowmap,
                                            int koff, int tid) {
#pragma unroll
    for (int i = 0; i < 2; i++) {
        int lin = tid + (i << 9);
        int row = lin >> 3, seg = lin & 7;
        cpa16(dst + swz((uint32_t)((row << 7) + (seg << 4))),
              base + (size_t)rowmap[row] * astride + koff + (seg << 3));
    }
}
__device__ __forceinline__ void load_w_tile(uint32_t dst, const __nv_bfloat16* __restrict__ src,
                                            int tid) {
    const char* s = (const char*)src;
#pragma unroll
    for (int i = 0; i < 4; i++) {
        uint32_t o = (uint32_t)((tid + (i << 9)) << 4);
        cpa16(dst + o, s + o);
    }
}

__device__ __forceinline__ void load_chunk(uint32_t sb, int c,
                                           const __nv_bfloat16* Ahi, const __nv_bfloat16* Alo,
                                           int astride, const int* rowmap,
                                           const __nv_bfloat16* Whi, const __nv_bfloat16* Wlo,
                                           int tid) {
    uint32_t st = sb + (c & 1) * STAGE_BYTES;
    int koff = c << 6;
    load_a_tile(st + SA_HI, Ahi, astride, rowmap, koff, tid);
    load_a_tile(st + SA_LO, Alo, astride, rowmap, koff, tid);
    load_w_tile(st + SW_HI, Whi + ((size_t)c << 14), tid);
    load_w_tile(st + SW_LO, Wlo + ((size_t)c << 14), tid);
    asm volatile("cp.async.commit_group;" ::: "memory");
}

// C(128x256) = Arows(128 x K) * W(256 x K)^T, hi/lo 3-pass bf16 via mma.sync
__device__ void tc_gemm(const __nv_bfloat16* __restrict__ Ahi,
                        const __nv_bfloat16* __restrict__ Alo, int astride, int kchunks,
                        const __nv_bfloat16* __restrict__ Whi,
                        const __nv_bfloat16* __restrict__ Wlo,
                        const int* __restrict__ rowmap, float* __restrict__ Cmn) {
    extern __shared__ char smem[];
    uint32_t sb = smem_to_u32(smem) + OFF_STAGE;
    const int tid = threadIdx.x;
    const int wid = tid >> 5;
    const int lid = tid & 31;
    const int wm = (wid >> 3) << 6;   // 0 or 64
    const int wn = (wid & 7) << 5;    // 0..224

    // ldmatrix lane-address components
    const int a_r = (lid & 7) | (((lid >> 3) & 1) << 3);
    const int a_kb = ((lid >> 4) & 1) << 4;
    const int w_r = (lid & 7) | (((lid >> 4) & 1) << 3);
    const int w_kb = ((lid >> 3) & 1) << 4;

    float acc[4][4][4];
#pragma unroll
    for (int i = 0; i < 4; i++)
#pragma unroll
        for (int j = 0; j < 4; j++)
#pragma unroll
            for (int q = 0; q < 4; q++) acc[i][j][q] = 0.f;

    load_chunk(sb, 0, Ahi, Alo, astride, rowmap, Whi, Wlo, tid);

    for (int c = 0; c < kchunks; c++) {
        if (c + 1 < kchunks) {
            load_chunk(sb, c + 1, Ahi, Alo, astride, rowmap, Whi, Wlo, tid);
            asm volatile("cp.async.wait_group 1;" ::: "memory");
        } else {
            asm volatile("cp.async.wait_group 0;" ::: "memory");
        }
        __syncthreads();
        uint32_t st = sb + (c & 1) * STAGE_BYTES;
#pragma unroll
        for (int ks = 0; ks < 4; ks++) {
            uint32_t wh[8], wl[8];
#pragma unroll
            for (int p = 0; p < 2; p++) {
                uint32_t off = swz((uint32_t)(((wn + (p << 4) + w_r) << 7) + (ks << 5) + w_kb));
                ldm_x4(wh + (p << 2), st + SW_HI + off);
                ldm_x4(wl + (p << 2), st + SW_LO + off);
            }
#pragma unroll
            for (int mt = 0; mt < 4; mt++) {
                uint32_t ah[4], al[4];
                uint32_t aoff = swz((uint32_t)(((wm + (mt << 4) + a_r) << 7) + (ks << 5) + a_kb));
                ldm_x4(ah, st + SA_HI + aoff);
                ldm_x4(al, st + SA_LO + aoff);
#pragma unroll
                for (int nt = 0; nt < 4; nt++) {
                    mma16816(acc[mt][nt], ah, wh + (nt << 1));
                    mma16816(acc[mt][nt], al, wh + (nt << 1));
                    mma16816(acc[mt][nt], ah, wl + (nt << 1));
                }
            }
        }
        __syncthreads();
    }

    // epilogue: fragment -> gmem
    const int mrow = lid >> 2;
    const int ncol = (lid & 3) << 1;
#pragma unroll
    for (int mt = 0; mt < 4; mt++) {
#pragma unroll
        for (int nt = 0; nt < 4; nt++) {
            float* c0 = Cmn + (size_t)(wm + (mt << 4) + mrow) * H3 + wn + (nt << 3) + ncol;
            *(float2*)c0 = make_float2(acc[mt][nt][0], acc[mt][nt][1]);
            *(float2*)(c0 + 8 * H3) = make_float2(acc[mt][nt][2], acc[mt][nt][3]);
        }
    }
}

// ==================== GEMM wrappers ====================
__global__ __launch_bounds__(512, 1) void pre_gemm_k() {
    __shared__ int rowmap[128];
    int m0 = blockIdx.y << 7;
    if (threadIdx.x < 128) rowmap[threadIdx.x] = m0 + threadIdx.x;
    __syncthreads();
    const __nv_bfloat16 *wh, *wl;
    float* C;
    if (blockIdx.z == 0)      { wh = d_wihE_s_hi; wl = d_wihE_s_lo; C = d_GI_s; }
    else if (blockIdx.z == 1) { wh = d_wihE_a_hi; wl = d_wihE_a_lo; C = d_GI_a; }
    else                      { wh = d_wihE_o_hi; wl = d_wihE_o_lo; C = d_GI_o; }
    int nt = blockIdx.x;
    size_t woff = (size_t)nt * 32 * 16384;  // 32 kchunks per 256-col ntile
    tc_gemm(d_enc_hi, d_enc_lo, E_, 32, wh + woff, wl + woff, rowmap,
            C + (size_t)m0 * H3 + nt * 256);
}

// virtual row layout in d_G (1280 rows x 3072):
//   [0,128) spk gh | [128,256) adr gh | [256,1024) oth gh |
//   [1024,1152) spk ih-state | [1152,1280) adr ih-state
__global__ __launch_bounds__(512, 1) void step_gemm_k(const int* __restrict__ dig, int t) {
    __shared__ int rowmap[128];
    int my = blockIdx.y;
    int m0 = my << 7;
    if (threadIdx.x < 128) {
        int i = threadIdx.x;
        int m = m0 + i;
        int b, role;
        if (m < 256 || m >= 1024) {
            b = i;
            int which = (my == 0) ? 0 : (my == 1) ? 1 : (my == 8) ? 1 : 0;
            role = dig[((size_t)(b * T_ + t)) * 2 + which];
        } else {
            int idx = m - 256;
            b = idx / 6;
            int k = idx % 6;
            int spk = dig[((size_t)(b * T_ + t)) * 2];
            int adr = dig[((size_t)(b * T_ + t)) * 2 + 1];
            int cnt = 0;
            role = 0;
#pragma unroll
            for (int rr = 0; rr < R_; rr++) {
                if (rr != spk && rr != adr) {
                    if (cnt == k) role = rr;
                    cnt++;
                }
            }
        }
        rowmap[i] = (b << 3) + role;
    }
    __syncthreads();
    const __nv_bfloat16 *wh, *wl;
    if (my == 0)      { wh = d_whh_s_hi;  wl = d_whh_s_lo; }
    else if (my == 1) { wh = d_whh_a_hi;  wl = d_whh_a_lo; }
    else if (my < 8)  { wh = d_whh_o_hi;  wl = d_whh_o_lo; }
    else if (my == 8) { wh = d_wihH_s_hi; wl = d_wihH_s_lo; }
    else              { wh = d_wihH_a_hi; wl = d_wihH_a_lo; }
    int nt = blockIdx.x;
    size_t woff = (size_t)nt * 16 * 16384;  // 16 kchunks per ntile
    tc_gemm(d_S_hi, d_S_lo, H_, 16, wh + woff, wl + woff, rowmap,
            d_G + (size_t)m0 * H3 + nt * 256);
}

// ==================== pointwise GRU update ====================
__global__ __launch_bounds__(256) void gru_pointwise(
    float* __restrict__ A, const int* __restrict__ dig, int t,
    const float* __restrict__ bih_s, const float* __restrict__ bhh_s,
    const float* __restrict__ bih_a, const float* __restrict__ bhh_a,
    const float* __restrict__ bih_o, const float* __restrict__ bhh_o) {
    int idx = blockIdx.x * 256 + threadIdx.x;
    int h = idx & (H_ - 1);
    int br = idx >> 10;
    int r = br & 7, b = br >> 3;
    int spk = dig[((size_t)(b * T_ + t)) * 2];
    int adr = dig[((size_t)(b * T_ + t)) * 2 + 1];
    const float *GI, *gihs = nullptr, *bih, *bhh;
    int ghrow;
    if (r == spk) {
        ghrow = b; gihs = d_G + (size_t)(1024 + b) * H3;
        GI = d_GI_s; bih = bih_s; bhh = bhh_s;
    } else if (r == adr) {
        ghrow = 128 + b; gihs = d_G + (size_t)(1152 + b) * H3;
        GI = d_GI_a; bih = bih_a; bhh = bhh_a;
    } else {
        int k = r - (spk < r ? 1 : 0) - (adr < r ? 1 : 0);
        ghrow = 256 + b * 6 + k;
        GI = d_GI_o; bih = bih_o; bhh = bhh_o;
    }
    const float* gi = GI + (size_t)(b * T_ + t) * H3;
    const float* gh = d_G + (size_t)ghrow * H3;
    float gir = gi[h] + bih[h];
    float giz = gi[H_ + h] + bih[H_ + h];
    float gin = gi[2 * H_ + h] + bih[2 * H_ + h];
    if (gihs) {
        gir += gihs[h];
        giz += gihs[H_ + h];
        gin += gihs[2 * H_ + h];
    }
    float ghr = gh[h] + bhh[h];
    float ghz = gh[H_ + h] + bhh[H_ + h];
    float ghn = gh[2 * H_ + h] + bhh[2 * H_ + h];
    float rg = 1.f / (1.f + expf(-(gir + ghr)));
    float zg = 1.f / (1.f + expf(-(giz + ghz)));
    float ng = tanhf(gin + rg * ghn);
    float hold = A[idx];
    float nv = (1.f - zg) * ng + zg * hold;
    A[idx] = nv;
    __nv_bfloat16 hh = __float2bfloat16(nv);
    d_S_hi[idx] = hh;
    d_S_lo[idx] = __float2bfloat16(nv - __bfloat162float(hh));
}

static void* sym_addr(const void* sym) {
    void* p = nullptr;
    cudaGetSymbolAddress(&p, sym);
    return p;
}

extern "C" void kernel_launch(void* const* d_in, const int* in_sizes, int n_in,
                              void* d_out, int out_size) {
    (void)in_sizes; (void)n_in; (void)out_size;
    const float* enc    = (const float*)d_in[0];
    const int*   dig    = (const int*)d_in[1];
    const float* ws_ih  = (const float*)d_in[2];
    const float* ws_hh  = (const float*)d_in[3];
    const float* ws_bih = (const float*)d_in[4];
    const float* ws_bhh = (const float*)d_in[5];
    const float* wa_ih  = (const float*)d_in[6];
    const float* wa_hh  = (const float*)d_in[7];
    const float* wa_bih = (const float*)d_in[8];
    const float* wa_bhh = (const float*)d_in[9];
    const float* wo_ih  = (const float*)d_in[10];
    const float* wo_hh  = (const float*)d_in[11];
    const float* wo_bih = (const float*)d_in[12];
    const float* wo_bhh = (const float*)d_in[13];
    float* A = (float*)d_out;

    cudaFuncSetAttribute(pre_gemm_k, cudaFuncAttributeMaxDynamicSharedMemorySize, SMEM_TOTAL);
    cudaFuncSetAttribute(step_gemm_k, cudaFuncAttributeMaxDynamicSharedMemorySize, SMEM_TOTAL);

    cudaMemsetAsync(d_out, 0, (size_t)B_ * R_ * H_ * sizeof(float), 0);
    cudaMemsetAsync(sym_addr(d_S_hi), 0, (size_t)B_ * R_ * H_ * 2, 0);
    cudaMemsetAsync(sym_addr(d_S_lo), 0, (size_t)B_ * R_ * H_ * 2, 0);

    conv_enc<<<(int)((size_t)B_ * T_ * E_ / 256), 256>>>(enc);
    conv_w<<<3072 * 1024 / 256, 256>>>(ws_hh, 1024, 0, 10,
        (__nv_bfloat16*)sym_addr(d_whh_s_hi), (__nv_bfloat16*)sym_addr(d_whh_s_lo));
    conv_w<<<3072 * 1024 / 256, 256>>>(wa_hh, 1024, 0, 10,
        (__nv_bfloat16*)sym_addr(d_whh_a_hi), (__nv_bfloat16*)sym_addr(d_whh_a_lo));
    conv_w<<<3072 * 1024 / 256, 256>>>(wo_hh, 1024, 0, 10,
        (__nv_bfloat16*)sym_addr(d_whh_o_hi), (__nv_bfloat16*)sym_addr(d_whh_o_lo));
    conv_w<<<3072 * 2048 / 256, 256>>>(ws_ih, 3072, 0, 11,
        (__nv_bfloat16*)sym_addr(d_wihE_s_hi), (__nv_bfloat16*)sym_addr(d_wihE_s_lo));
    conv_w<<<3072 * 2048 / 256, 256>>>(wa_ih, 3072, 0, 11,
        (__nv_bfloat16*)sym_addr(d_wihE_a_hi), (__nv_bfloat16*)sym_addr(d_wihE_a_lo));
    conv_w<<<3072 * 2048 / 256, 256>>>(wo_ih, 2048, 0, 11,
        (__nv_bfloat16*)sym_addr(d_wihE_o_hi), (__nv_bfloat16*)sym_addr(d_wihE_o_lo));
    conv_w<<<3072 * 1024 / 256, 256>>>(ws_ih, 3072, 2048, 10,
        (__nv_bfloat16*)sym_addr(d_wihH_s_hi), (__nv_bfloat16*)sym_addr(d_wihH_s_lo));
    conv_w<<<3072 * 1024 / 256, 256>>>(wa_ih, 3072, 2048, 10,
        (__nv_bfloat16*)sym_addr(d_wihH_a_hi), (__nv_bfloat16*)sym_addr(d_wihH_a_lo));

    // state-independent gi precompute: 12 ntiles x 64 mtiles x 3 matrices
    pre_gemm_k<<<dim3(12, 64, 3), 512, SMEM_TOTAL>>>();

    // sequential scan
    for (int t = 0; t < T_; t++) {
        step_gemm_k<<<dim3(12, 10), 512, SMEM_TOTAL>>>(dig, t);
        gru_pointwise<<<4096, 256>>>(A, dig, t, ws_bih, ws_bhh, wa_bih, wa_bhh,
                                     wo_bih, wo_bhh);
    }
}